// round 15
// baseline (speedup 1.0000x reference)
#include <cuda_runtime.h>
#include <math.h>

#define NLEVELS 16
#define TSIZE (1u << 19)
#define TMASK (TSIZE - 1u)
#define HIDDEN 64
#define INDIM 32
#define OUTDIM 16
#define P2 2654435761u
#define P3 805459861u
#define TPB 256
#define NDENSE 6

#define DSZ0 4370
#define DSZ1 12721
#define DSZ2 30785
#define DSZ3 81401
#define DSZ4 208921
#define DSZ5 551368
#define DOFF0 0
#define DOFF1 (DOFF0 + DSZ0)
#define DOFF2 (DOFF1 + DSZ1)
#define DOFF3 (DOFF2 + DSZ2)
#define DOFF4 (DOFF3 + DSZ3)
#define DOFF5 (DOFF4 + DSZ4)
#define DTOT  (DOFF5 + DSZ5)

#define OW1  2048
#define OB0  3072
#define OB1  3136
#define CTOT 3152

__device__ float4 gDense[DTOT];
__device__ __align__(16) float gStage[CTOT];

__constant__ __align__(16) float cAll[CTOT];

struct Params {
    float scale[NLEVELS];
};

typedef unsigned long long u64;

__device__ __forceinline__ u64 pk2(float lo, float hi) {
    u64 r;
    asm("mov.b64 %0, {%1, %2};" : "=l"(r) : "f"(lo), "f"(hi));
    return r;
}
__device__ __forceinline__ void upk2(float& lo, float& hi, u64 v) {
    asm("mov.b64 {%0, %1}, %2;" : "=f"(lo), "=f"(hi) : "l"(v));
}
__device__ __forceinline__ u64 fma2(u64 a, u64 b, u64 c) {
    u64 r;
    asm("fma.rn.f32x2 %0, %1, %2, %3;" : "=l"(r) : "l"(a), "l"(b), "l"(c));
    return r;
}
__device__ __forceinline__ u64 mul2(u64 a, u64 b) {
    u64 r;
    asm("mul.rn.f32x2 %0, %1, %2;" : "=l"(r) : "l"(a), "l"(b));
    return r;
}

__device__ __forceinline__ float2 cond_ldg_f2_indep(const float2* addr, unsigned cond) {
    float2 r;
    asm("{\n\t"
        ".reg .pred p;\n\t"
        "setp.ne.u32 p, %2, 0;\n\t"
        "mov.f32 %0, 0f00000000;\n\t"
        "mov.f32 %1, 0f00000000;\n\t"
        "@p ld.global.nc.v2.f32 {%0,%1}, [%3];\n\t"
        "}"
        : "=f"(r.x), "=f"(r.y)
        : "r"(cond), "l"(addr));
    return r;
}

__global__ void setup_kernel(const float* __restrict__ table,
                             const float* __restrict__ W0,
                             const float* __restrict__ b0,
                             const float* __restrict__ W1,
                             const float* __restrict__ b1)
{
    int t = blockIdx.x * blockDim.x + threadIdx.x;

    if (t < CTOT) {
        float v;
        if (t < OW1) {
            v = W0[t];
        } else if (t < OB0) {
            int u = t - OW1;
            int j = u >> 4, o = u & 15;
            v = W1[o * HIDDEN + j];
        } else if (t < OB1) {
            v = b0[t - OB0];
        } else {
            v = b1[t - OB1];
        }
        gStage[t] = v;
    }

    if (t >= DTOT) return;

    if (t < DOFF5) {
        int l, off;
        if      (t < DOFF1) { l = 0; off = DOFF0; }
        else if (t < DOFF2) { l = 1; off = DOFF1; }
        else if (t < DOFF3) { l = 2; off = DOFF2; }
        else if (t < DOFF4) { l = 3; off = DOFF3; }
        else                { l = 4; off = DOFF4; }
        unsigned j = t - off;
        const float2* tl = (const float2*)table + (size_t)l * TSIZE;
        float2 a = tl[j];
        float2 b = tl[j + 1];
        gDense[t] = make_float4(a.x, a.y, b.x, b.y);
    } else {
        unsigned j = t - DOFF5;
        unsigned cz = j / 6724u;
        unsigned rem = j - cz * 6724u;
        unsigned cy = rem / 82u;
        unsigned cx = rem - cy * 82u;
        unsigned H = cy * P2 ^ cz * P3;
        const float2* tl = (const float2*)table + (size_t)5 * TSIZE;
        float2 a = tl[(cx ^ H) & TMASK];
        float2 b = tl[((cx + 1u) ^ H) & TMASK];
        gDense[t] = make_float4(a.x, a.y, b.x, b.y);
    }
}

__global__ __launch_bounds__(TPB, 4) void sdf_fused_kernel(
    const float* __restrict__ x,
    const float* __restrict__ table,
    float* __restrict__ out,
    int N, Params p)
{
    __shared__ __align__(16) float sGeo[TPB * 15];

    int tid = threadIdx.x;
    int iBase = blockIdx.x * TPB;
    int i = iBase + tid;
    bool valid = (i < N);
    int ii = valid ? i : 0;

    float x0 = x[3 * ii + 0];
    float x1 = x[3 * ii + 1];
    float x2 = x[3 * ii + 2];
    float ux = fminf(fmaxf((x0 + 1.0f) * 0.5f, 0.0f), 1.0f);
    float uy = fminf(fmaxf((x1 + 1.0f) * 0.5f, 0.0f), 1.0f);
    float uz = fminf(fmaxf((x2 + 1.0f) * 0.5f, 0.0f), 1.0f);

    u64 enc2[NLEVELS];
    const float2* __restrict__ tab = (const float2*)table;

    const unsigned kSTR[NDENSE] = {16u, 23u, 31u, 43u, 59u, 82u};
    const unsigned kOFF[NDENSE] = {DOFF0, DOFF1, DOFF2, DOFF3, DOFF4, DOFF5};

    // ---- dense levels 0-5: compile-time strides, fully unrolled ----
#pragma unroll
    for (int l = 0; l < NDENSE; l++) {
        float s = p.scale[l];
        float px = fmaf(ux, s, 0.5f);
        float py = fmaf(uy, s, 0.5f);
        float pz = fmaf(uz, s, 0.5f);
        float gx = floorf(px), gy = floorf(py), gz = floorf(pz);
        float fx = px - gx, fy = py - gy, fz = pz - gz;
        unsigned cx = (unsigned)gx, cy = (unsigned)gy, cz = (unsigned)gz;

        float wx0 = 1.0f - fx;
        float wy0 = 1.0f - fy, wz0 = 1.0f - fz;
        u64 fx2 = pk2(fx, fx);
        u64 wx02 = pk2(wx0, wx0);
        u64 acc = pk2(0.0f, 0.0f);

        float wyzA[4];
        wyzA[0] = wy0 * wz0;
        wyzA[1] = fy  * wz0;
        wyzA[2] = wy0 * fz;
        wyzA[3] = fy  * fz;

        unsigned r = kSTR[l], r2 = r * r;
        unsigned b00 = kOFF[l] + cx + cy * r + cz * r2;
        unsigned bA[4] = {b00, b00 + r, b00 + r2, b00 + r + r2};
        float4 v[4];
#pragma unroll
        for (int c = 0; c < 4; c++) v[c] = __ldg(&gDense[bA[c]]);
#pragma unroll
        for (int c = 0; c < 4; c++) {
            u64 t = mul2(pk2(v[c].x, v[c].y), wx02);
            t = fma2(pk2(v[c].z, v[c].w), fx2, t);
            acc = fma2(t, pk2(wyzA[c], wyzA[c]), acc);
        }
        enc2[l] = acc;
    }

    // ---- hashed levels 6-15: rolled loop, 2 levels in flight ----
#pragma unroll 2
    for (int l = NDENSE; l < NLEVELS; l++) {
        float s = p.scale[l];
        float px = fmaf(ux, s, 0.5f);
        float py = fmaf(uy, s, 0.5f);
        float pz = fmaf(uz, s, 0.5f);
        float gx = floorf(px), gy = floorf(py), gz = floorf(pz);
        float fx = px - gx, fy = py - gy, fz = pz - gz;
        unsigned cx = (unsigned)gx, cy = (unsigned)gy, cz = (unsigned)gz;

        float wx0 = 1.0f - fx;
        float wy0 = 1.0f - fy, wz0 = 1.0f - fz;
        u64 fx2 = pk2(fx, fx);
        u64 wx02 = pk2(wx0, wx0);
        u64 acc = pk2(0.0f, 0.0f);

        float wyzA[4];
        wyzA[0] = wy0 * wz0;
        wyzA[1] = fy  * wz0;
        wyzA[2] = wy0 * fz;
        wyzA[3] = fy  * fz;

        const float2* __restrict__ tl = tab + (size_t)l * TSIZE;
        const float4* __restrict__ tl4 = (const float4*)tl;
        unsigned ty0 = cy * P2, ty1 = ty0 + P2;
        unsigned tz0 = cz * P3, tz1 = tz0 + P3;
        unsigned mask = cx ^ (cx + 1u);
        unsigned np = cx & 1u;

        float4 v[4];
        float2 t2[4];
        unsigned jloA[4];
#pragma unroll
        for (int c = 0; c < 4; c++) {
            unsigned H = ((c & 1u) ? ty1 : ty0) ^ ((c & 2u) ? tz1 : tz0);
            unsigned jlo = (cx ^ H) & TMASK;
            unsigned jhi = (jlo ^ mask) & TMASK;
            jloA[c] = jlo;
            v[c] = __ldg(tl4 + (jlo >> 1));
            t2[c] = cond_ldg_f2_indep(tl + jhi, np);
        }
#pragma unroll
        for (int c = 0; c < 4; c++) {
            unsigned odd = jloA[c] & 1u;
            float2 flo = odd ? make_float2(v[c].z, v[c].w) : make_float2(v[c].x, v[c].y);
            float2 oth = odd ? make_float2(v[c].x, v[c].y) : make_float2(v[c].z, v[c].w);
            float2 fhi = np ? t2[c] : oth;
            u64 t = mul2(pk2(flo.x, flo.y), wx02);
            t = fma2(pk2(fhi.x, fhi.y), fx2, t);
            acc = fma2(t, pk2(wyzA[c], wyzA[c]), acc);
        }
        enc2[l] = acc;
    }

    // ---- MLP with packed f32x2 FMA; weights from constant ----
    const u64* __restrict__ w0q = (const u64*)cAll;
    const u64* __restrict__ w1q = (const u64*)(cAll + OW1);
    const float* __restrict__ cb0 = cAll + OB0;
    const float* __restrict__ cb1 = cAll + OB1;

    u64 acc2[OUTDIM / 2];
#pragma unroll
    for (int o2 = 0; o2 < OUTDIM / 2; o2++)
        acc2[o2] = pk2(cb1[2 * o2], cb1[2 * o2 + 1]);

#pragma unroll 4
    for (int j = 0; j < HIDDEN; j++) {
        u64 h2 = pk2(cb0[j], 0.0f);
#pragma unroll
        for (int k2 = 0; k2 < NLEVELS; k2++)
            h2 = fma2(enc2[k2], w0q[j * NLEVELS + k2], h2);
        float hlo, hhi;
        upk2(hlo, hhi, h2);
        float h = hlo + hhi;

        float z = 100.0f * h;
        float sp = __logf(1.0f + __expf(z)) * 0.01f;
        float a = (z > 20.0f) ? h : sp;

        u64 a2 = pk2(a, a);
#pragma unroll
        for (int o2 = 0; o2 < OUTDIM / 2; o2++)
            acc2[o2] = fma2(a2, w1q[j * (OUTDIM / 2) + o2], acc2[o2]);
    }

    float acc[OUTDIM];
#pragma unroll
    for (int o2 = 0; o2 < OUTDIM / 2; o2++)
        upk2(acc[2 * o2], acc[2 * o2 + 1], acc2[o2]);

#pragma unroll
    for (int o = 0; o < 15; o++) sGeo[tid * 15 + o] = acc[o + 1];
    if (valid) out[i] = acc[0];
    __syncthreads();

    float* __restrict__ geo = out + N;
    size_t gbase = (size_t)iBase * 15;
    int remain = N - iBase;
    if (remain >= TPB) {
        const float4* __restrict__ s4 = (const float4*)sGeo;
        float4* __restrict__ g4 = (float4*)(geo + gbase);
        for (int t = tid; t < TPB * 15 / 4; t += TPB)
            g4[t] = s4[t];
    } else {
        int total = remain * 15;
        for (int t = tid; t < total; t += TPB)
            geo[gbase + t] = sGeo[t];
    }
}

extern "C" void kernel_launch(void* const* d_in, const int* in_sizes, int n_in,
                              void* d_out, int out_size)
{
    const float* x     = (const float*)d_in[0];
    const float* table = (const float*)d_in[1];
    const float* W0    = (const float*)d_in[2];
    const float* b0    = (const float*)d_in[3];
    const float* W1    = (const float*)d_in[4];
    const float* b1    = (const float*)d_in[5];
    float* out = (float*)d_out;

    int N = in_sizes[0] / 3;

    setup_kernel<<<(DTOT + 255) / 256, 256>>>(table, W0, b0, W1, b1);
    void* stage = nullptr;
    cudaGetSymbolAddress(&stage, gStage);
    cudaMemcpyToSymbolAsync(cAll, stage, CTOT * sizeof(float), 0,
                            cudaMemcpyDeviceToDevice, 0);

    Params p;
    const double pls = exp2(7.0 / 15.0);
    for (int l = 0; l < NLEVELS; l++) {
        double sc = 16.0 * pow(pls, (double)l) - 1.0;
        p.scale[l] = (float)sc;
    }

    int blocks = (N + TPB - 1) / TPB;
    sdf_fused_kernel<<<blocks, TPB>>>(x, table, out, N, p);
}

// round 16
// speedup vs baseline: 1.1734x; 1.1734x over previous
#include <cuda_runtime.h>
#include <math.h>

#define NLEVELS 16
#define TSIZE (1u << 19)
#define TMASK (TSIZE - 1u)
#define HIDDEN 64
#define INDIM 32
#define OUTDIM 16
#define P2 2654435761u
#define P3 805459861u
#define TPB 256
#define NDENSE 6

#define DSZ0 4370
#define DSZ1 12721
#define DSZ2 30785
#define DSZ3 81401
#define DSZ4 208921
#define DSZ5 551368
#define DOFF0 0
#define DOFF1 (DOFF0 + DSZ0)
#define DOFF2 (DOFF1 + DSZ1)
#define DOFF3 (DOFF2 + DSZ2)
#define DOFF4 (DOFF3 + DSZ3)
#define DOFF5 (DOFF4 + DSZ4)
#define DTOT  (DOFF5 + DSZ5)

#define OW1  2048
#define OB0  3072
#define OB1  3136
#define CTOT 3152

__device__ float4 gDense[DTOT];
__device__ __align__(16) float gStage[CTOT];

__constant__ __align__(16) float cAll[CTOT];

struct Params {
    float scale[NLEVELS];
};

typedef unsigned long long u64;

__device__ __forceinline__ u64 pk2(float lo, float hi) {
    u64 r;
    asm("mov.b64 %0, {%1, %2};" : "=l"(r) : "f"(lo), "f"(hi));
    return r;
}
__device__ __forceinline__ void upk2(float& lo, float& hi, u64 v) {
    asm("mov.b64 {%0, %1}, %2;" : "=f"(lo), "=f"(hi) : "l"(v));
}
__device__ __forceinline__ u64 fma2(u64 a, u64 b, u64 c) {
    u64 r;
    asm("fma.rn.f32x2 %0, %1, %2, %3;" : "=l"(r) : "l"(a), "l"(b), "l"(c));
    return r;
}
__device__ __forceinline__ u64 mul2(u64 a, u64 b) {
    u64 r;
    asm("mul.rn.f32x2 %0, %1, %2;" : "=l"(r) : "l"(a), "l"(b));
    return r;
}

__device__ __forceinline__ float2 cond_ldg_f2_indep(const float2* addr, unsigned cond) {
    float2 r;
    asm("{\n\t"
        ".reg .pred p;\n\t"
        "setp.ne.u32 p, %2, 0;\n\t"
        "mov.f32 %0, 0f00000000;\n\t"
        "mov.f32 %1, 0f00000000;\n\t"
        "@p ld.global.nc.v2.f32 {%0,%1}, [%3];\n\t"
        "}"
        : "=f"(r.x), "=f"(r.y)
        : "r"(cond), "l"(addr));
    return r;
}

__global__ void setup_kernel(const float* __restrict__ table,
                             const float* __restrict__ W0,
                             const float* __restrict__ b0,
                             const float* __restrict__ W1,
                             const float* __restrict__ b1)
{
    int t = blockIdx.x * blockDim.x + threadIdx.x;

    if (t < CTOT) {
        float v;
        if (t < OW1) {
            v = W0[t];
        } else if (t < OB0) {
            int u = t - OW1;
            int j = u >> 4, o = u & 15;
            v = W1[o * HIDDEN + j];
        } else if (t < OB1) {
            v = b0[t - OB0];
        } else {
            v = b1[t - OB1];
        }
        gStage[t] = v;
    }

    if (t >= DTOT) return;

    if (t < DOFF5) {
        int l, off;
        if      (t < DOFF1) { l = 0; off = DOFF0; }
        else if (t < DOFF2) { l = 1; off = DOFF1; }
        else if (t < DOFF3) { l = 2; off = DOFF2; }
        else if (t < DOFF4) { l = 3; off = DOFF3; }
        else                { l = 4; off = DOFF4; }
        unsigned j = t - off;
        const float2* tl = (const float2*)table + (size_t)l * TSIZE;
        float2 a = tl[j];
        float2 b = tl[j + 1];
        gDense[t] = make_float4(a.x, a.y, b.x, b.y);
    } else {
        unsigned j = t - DOFF5;
        unsigned cz = j / 6724u;
        unsigned rem = j - cz * 6724u;
        unsigned cy = rem / 82u;
        unsigned cx = rem - cy * 82u;
        unsigned H = cy * P2 ^ cz * P3;
        const float2* tl = (const float2*)table + (size_t)5 * TSIZE;
        float2 a = tl[(cx ^ H) & TMASK];
        float2 b = tl[((cx + 1u) ^ H) & TMASK];
        gDense[t] = make_float4(a.x, a.y, b.x, b.y);
    }
}

__global__ __launch_bounds__(TPB, 4) void sdf_fused_kernel(
    const float* __restrict__ x,
    const float* __restrict__ table,
    float* __restrict__ out,
    int N, Params p)
{
    __shared__ __align__(16) float sGeo[TPB * 15];

    int tid = threadIdx.x;
    int iBase = blockIdx.x * TPB;
    int i = iBase + tid;
    bool valid = (i < N);
    int ii = valid ? i : 0;

    float x0 = x[3 * ii + 0];
    float x1 = x[3 * ii + 1];
    float x2 = x[3 * ii + 2];
    float ux = fminf(fmaxf((x0 + 1.0f) * 0.5f, 0.0f), 1.0f);
    float uy = fminf(fmaxf((x1 + 1.0f) * 0.5f, 0.0f), 1.0f);
    float uz = fminf(fmaxf((x2 + 1.0f) * 0.5f, 0.0f), 1.0f);

    u64 enc2[NLEVELS];
    const float2* __restrict__ tab = (const float2*)table;

    const unsigned kSTR[NDENSE] = {16u, 23u, 31u, 43u, 59u, 82u};
    const unsigned kOFF[NDENSE] = {DOFF0, DOFF1, DOFF2, DOFF3, DOFF4, DOFF5};

#pragma unroll
    for (int l = 0; l < NLEVELS; l++) {
        float s = p.scale[l];
        float px = fmaf(ux, s, 0.5f);
        float py = fmaf(uy, s, 0.5f);
        float pz = fmaf(uz, s, 0.5f);
        float gx = floorf(px), gy = floorf(py), gz = floorf(pz);
        float fx = px - gx, fy = py - gy, fz = pz - gz;
        unsigned cx = (unsigned)gx, cy = (unsigned)gy, cz = (unsigned)gz;

        float wx0 = 1.0f - fx;
        float wy0 = 1.0f - fy, wz0 = 1.0f - fz;
        u64 fx2 = pk2(fx, fx);
        u64 wx02 = pk2(wx0, wx0);
        u64 acc = pk2(0.0f, 0.0f);

        float wyzA[4];
        wyzA[0] = wy0 * wz0;
        wyzA[1] = fy  * wz0;
        wyzA[2] = wy0 * fz;
        wyzA[3] = fy  * fz;

        if (l < NDENSE) {
            unsigned r = kSTR[l], r2 = r * r;
            unsigned b00 = kOFF[l] + cx + cy * r + cz * r2;
            unsigned bA[4] = {b00, b00 + r, b00 + r2, b00 + r + r2};
            float4 v[4];
#pragma unroll
            for (int c = 0; c < 4; c++) v[c] = __ldg(&gDense[bA[c]]);
#pragma unroll
            for (int c = 0; c < 4; c++) {
                u64 t = mul2(pk2(v[c].x, v[c].y), wx02);
                t = fma2(pk2(v[c].z, v[c].w), fx2, t);
                acc = fma2(t, pk2(wyzA[c], wyzA[c]), acc);
            }
        } else {
            const float2* __restrict__ tl = tab + (size_t)l * TSIZE;
            const float4* __restrict__ tl4 = (const float4*)tl;
            unsigned ty0 = cy * P2, ty1 = ty0 + P2;
            unsigned tz0 = cz * P3, tz1 = tz0 + P3;
            unsigned mask = cx ^ (cx + 1u);
            unsigned np = cx & 1u;

            float4 v[4];
            float2 t2[4];
            unsigned jloA[4];
#pragma unroll
            for (int c = 0; c < 4; c++) {
                unsigned H = ((c & 1u) ? ty1 : ty0) ^ ((c & 2u) ? tz1 : tz0);
                unsigned jlo = (cx ^ H) & TMASK;
                unsigned jhi = (jlo ^ mask) & TMASK;
                jloA[c] = jlo;
                v[c] = __ldg(tl4 + (jlo >> 1));
                t2[c] = cond_ldg_f2_indep(tl + jhi, np);
            }
#pragma unroll
            for (int c = 0; c < 4; c++) {
                unsigned odd = jloA[c] & 1u;
                float2 flo = odd ? make_float2(v[c].z, v[c].w) : make_float2(v[c].x, v[c].y);
                float2 oth = odd ? make_float2(v[c].x, v[c].y) : make_float2(v[c].z, v[c].w);
                float2 fhi = np ? t2[c] : oth;
                u64 t = mul2(pk2(flo.x, flo.y), wx02);
                t = fma2(pk2(fhi.x, fhi.y), fx2, t);
                acc = fma2(t, pk2(wyzA[c], wyzA[c]), acc);
            }
        }
        enc2[l] = acc;
    }

    const u64* __restrict__ w0q = (const u64*)cAll;
    const u64* __restrict__ w1q = (const u64*)(cAll + OW1);
    const float* __restrict__ cb0 = cAll + OB0;
    const float* __restrict__ cb1 = cAll + OB1;

    u64 acc2[OUTDIM / 2];
#pragma unroll
    for (int o2 = 0; o2 < OUTDIM / 2; o2++)
        acc2[o2] = pk2(cb1[2 * o2], cb1[2 * o2 + 1]);

#pragma unroll 8
    for (int j = 0; j < HIDDEN; j++) {
        u64 h2 = pk2(cb0[j], 0.0f);
#pragma unroll
        for (int k2 = 0; k2 < NLEVELS; k2++)
            h2 = fma2(enc2[k2], w0q[j * NLEVELS + k2], h2);
        float hlo, hhi;
        upk2(hlo, hhi, h2);
        float h = hlo + hhi;

        float z = 100.0f * h;
        float sp = __logf(1.0f + __expf(z)) * 0.01f;
        float a = (z > 20.0f) ? h : sp;

        u64 a2 = pk2(a, a);
#pragma unroll
        for (int o2 = 0; o2 < OUTDIM / 2; o2++)
            acc2[o2] = fma2(a2, w1q[j * (OUTDIM / 2) + o2], acc2[o2]);
    }

    float acc[OUTDIM];
#pragma unroll
    for (int o2 = 0; o2 < OUTDIM / 2; o2++)
        upk2(acc[2 * o2], acc[2 * o2 + 1], acc2[o2]);

#pragma unroll
    for (int o = 0; o < 15; o++) sGeo[tid * 15 + o] = acc[o + 1];
    if (valid) out[i] = acc[0];
    __syncthreads();

    float* __restrict__ geo = out + N;
    size_t gbase = (size_t)iBase * 15;
    int remain = N - iBase;
    if (remain >= TPB) {
        const float4* __restrict__ s4 = (const float4*)sGeo;
        float4* __restrict__ g4 = (float4*)(geo + gbase);
        for (int t = tid; t < TPB * 15 / 4; t += TPB)
            g4[t] = s4[t];
    } else {
        int total = remain * 15;
        for (int t = tid; t < total; t += TPB)
            geo[gbase + t] = sGeo[t];
    }
}

extern "C" void kernel_launch(void* const* d_in, const int* in_sizes, int n_in,
                              void* d_out, int out_size)
{
    const float* x     = (const float*)d_in[0];
    const float* table = (const float*)d_in[1];
    const float* W0    = (const float*)d_in[2];
    const float* b0    = (const float*)d_in[3];
    const float* W1    = (const float*)d_in[4];
    const float* b1    = (const float*)d_in[5];
    float* out = (float*)d_out;

    int N = in_sizes[0] / 3;

    setup_kernel<<<(DTOT + 255) / 256, 256>>>(table, W0, b0, W1, b1);
    void* stage = nullptr;
    cudaGetSymbolAddress(&stage, gStage);
    cudaMemcpyToSymbolAsync(cAll, stage, CTOT * sizeof(float), 0,
                            cudaMemcpyDeviceToDevice, 0);

    Params p;
    const double pls = exp2(7.0 / 15.0);
    for (int l = 0; l < NLEVELS; l++) {
        double sc = 16.0 * pow(pls, (double)l) - 1.0;
        p.scale[l] = (float)sc;
    }

    int blocks = (N + TPB - 1) / TPB;
    sdf_fused_kernel<<<blocks, TPB>>>(x, table, out, N, p);
}

// round 17
// speedup vs baseline: 1.1856x; 1.0105x over previous
#include <cuda_runtime.h>
#include <math.h>

#define NLEVELS 16
#define TSIZE (1u << 19)
#define TMASK (TSIZE - 1u)
#define HIDDEN 64
#define INDIM 32
#define OUTDIM 16
#define P2 2654435761u
#define P3 805459861u
#define TPB 256
#define NDENSE 6

#define DSZ0 4370
#define DSZ1 12721
#define DSZ2 30785
#define DSZ3 81401
#define DSZ4 208921
#define DSZ5 551368
#define DOFF0 0
#define DOFF1 (DOFF0 + DSZ0)
#define DOFF2 (DOFF1 + DSZ1)
#define DOFF3 (DOFF2 + DSZ2)
#define DOFF4 (DOFF3 + DSZ3)
#define DOFF5 (DOFF4 + DSZ4)
#define DTOT  (DOFF5 + DSZ5)

#define OW1  2048
#define OB0  3072
#define OB1  3136
#define CTOT 3152

// shared buffer: first phase = level-0 table (4370 float2 = 8740 floats),
// second phase = sGeo staging (TPB*15 = 3840 floats). Aliased.
#define SBUF_FLOATS 8744   /* 8740 rounded up to multiple of 4 */

__device__ float4 gDense[DTOT];
__device__ __align__(16) float gStage[CTOT];

__constant__ __align__(16) float cAll[CTOT];

struct Params {
    float scale[NLEVELS];
};

typedef unsigned long long u64;

__device__ __forceinline__ u64 pk2(float lo, float hi) {
    u64 r;
    asm("mov.b64 %0, {%1, %2};" : "=l"(r) : "f"(lo), "f"(hi));
    return r;
}
__device__ __forceinline__ void upk2(float& lo, float& hi, u64 v) {
    asm("mov.b64 {%0, %1}, %2;" : "=f"(lo), "=f"(hi) : "l"(v));
}
__device__ __forceinline__ u64 fma2(u64 a, u64 b, u64 c) {
    u64 r;
    asm("fma.rn.f32x2 %0, %1, %2, %3;" : "=l"(r) : "l"(a), "l"(b), "l"(c));
    return r;
}
__device__ __forceinline__ u64 mul2(u64 a, u64 b) {
    u64 r;
    asm("mul.rn.f32x2 %0, %1, %2;" : "=l"(r) : "l"(a), "l"(b));
    return r;
}

__device__ __forceinline__ float2 cond_ldg_f2_indep(const float2* addr, unsigned cond) {
    float2 r;
    asm("{\n\t"
        ".reg .pred p;\n\t"
        "setp.ne.u32 p, %2, 0;\n\t"
        "mov.f32 %0, 0f00000000;\n\t"
        "mov.f32 %1, 0f00000000;\n\t"
        "@p ld.global.nc.v2.f32 {%0,%1}, [%3];\n\t"
        "}"
        : "=f"(r.x), "=f"(r.y)
        : "r"(cond), "l"(addr));
    return r;
}

__global__ void setup_kernel(const float* __restrict__ table,
                             const float* __restrict__ W0,
                             const float* __restrict__ b0,
                             const float* __restrict__ W1,
                             const float* __restrict__ b1)
{
    int t = blockIdx.x * blockDim.x + threadIdx.x;

    if (t < CTOT) {
        float v;
        if (t < OW1) {
            v = W0[t];
        } else if (t < OB0) {
            int u = t - OW1;
            int j = u >> 4, o = u & 15;
            v = W1[o * HIDDEN + j];
        } else if (t < OB1) {
            v = b0[t - OB0];
        } else {
            v = b1[t - OB1];
        }
        gStage[t] = v;
    }

    if (t >= DTOT) return;

    if (t < DOFF5) {
        int l, off;
        if      (t < DOFF1) { l = 0; off = DOFF0; }
        else if (t < DOFF2) { l = 1; off = DOFF1; }
        else if (t < DOFF3) { l = 2; off = DOFF2; }
        else if (t < DOFF4) { l = 3; off = DOFF3; }
        else                { l = 4; off = DOFF4; }
        unsigned j = t - off;
        const float2* tl = (const float2*)table + (size_t)l * TSIZE;
        float2 a = tl[j];
        float2 b = tl[j + 1];
        gDense[t] = make_float4(a.x, a.y, b.x, b.y);
    } else {
        unsigned j = t - DOFF5;
        unsigned cz = j / 6724u;
        unsigned rem = j - cz * 6724u;
        unsigned cy = rem / 82u;
        unsigned cx = rem - cy * 82u;
        unsigned H = cy * P2 ^ cz * P3;
        const float2* tl = (const float2*)table + (size_t)5 * TSIZE;
        float2 a = tl[(cx ^ H) & TMASK];
        float2 b = tl[((cx + 1u) ^ H) & TMASK];
        gDense[t] = make_float4(a.x, a.y, b.x, b.y);
    }
}

__global__ __launch_bounds__(TPB, 4) void sdf_fused_kernel(
    const float* __restrict__ x,
    const float* __restrict__ table,
    float* __restrict__ out,
    int N, Params p)
{
    __shared__ __align__(16) float sBuf[SBUF_FLOATS];

    int tid = threadIdx.x;
    int iBase = blockIdx.x * TPB;
    int i = iBase + tid;
    bool valid = (i < N);
    int ii = valid ? i : 0;

    // phase 1: stage level-0 table (4370 float2 = 8740 floats) into shared
    {
        const float4* __restrict__ src = (const float4*)table;  // level 0 base
        float4* __restrict__ dst = (float4*)sBuf;
        for (int t = tid; t < SBUF_FLOATS / 4; t += TPB)
            dst[t] = src[t];   // reads a few floats past 8740 - within table
    }

    float x0 = x[3 * ii + 0];
    float x1 = x[3 * ii + 1];
    float x2 = x[3 * ii + 2];
    float ux = fminf(fmaxf((x0 + 1.0f) * 0.5f, 0.0f), 1.0f);
    float uy = fminf(fmaxf((x1 + 1.0f) * 0.5f, 0.0f), 1.0f);
    float uz = fminf(fmaxf((x2 + 1.0f) * 0.5f, 0.0f), 1.0f);

    __syncthreads();  // sTab ready

    u64 enc2[NLEVELS];
    const float2* __restrict__ tab = (const float2*)table;
    const float2* __restrict__ sTab = (const float2*)sBuf;

    const unsigned kSTR[NDENSE] = {16u, 23u, 31u, 43u, 59u, 82u};
    const unsigned kOFF[NDENSE] = {DOFF0, DOFF1, DOFF2, DOFF3, DOFF4, DOFF5};

#pragma unroll
    for (int l = 0; l < NLEVELS; l++) {
        float s = p.scale[l];
        float px = fmaf(ux, s, 0.5f);
        float py = fmaf(uy, s, 0.5f);
        float pz = fmaf(uz, s, 0.5f);
        float gx = floorf(px), gy = floorf(py), gz = floorf(pz);
        float fx = px - gx, fy = py - gy, fz = pz - gz;
        unsigned cx = (unsigned)gx, cy = (unsigned)gy, cz = (unsigned)gz;

        float wx0 = 1.0f - fx;
        float wy0 = 1.0f - fy, wz0 = 1.0f - fz;
        u64 fx2 = pk2(fx, fx);
        u64 wx02 = pk2(wx0, wx0);
        u64 acc = pk2(0.0f, 0.0f);

        float wyzA[4];
        wyzA[0] = wy0 * wz0;
        wyzA[1] = fy  * wz0;
        wyzA[2] = wy0 * fz;
        wyzA[3] = fy  * fz;

        if (l == 0) {
            // level 0 from shared memory: 8 LDS.64, conflict-cheap
            unsigned b00 = cx + cy * 16u + cz * 256u;
            unsigned bA[4] = {b00, b00 + 16u, b00 + 256u, b00 + 272u};
#pragma unroll
            for (int c = 0; c < 4; c++) {
                float2 lo = sTab[bA[c]];
                float2 hi = sTab[bA[c] + 1u];
                u64 t = mul2(pk2(lo.x, lo.y), wx02);
                t = fma2(pk2(hi.x, hi.y), fx2, t);
                acc = fma2(t, pk2(wyzA[c], wyzA[c]), acc);
            }
        } else if (l < NDENSE) {
            unsigned r = kSTR[l], r2 = r * r;
            unsigned b00 = kOFF[l] + cx + cy * r + cz * r2;
            unsigned bA[4] = {b00, b00 + r, b00 + r2, b00 + r + r2};
            float4 v[4];
#pragma unroll
            for (int c = 0; c < 4; c++) v[c] = __ldg(&gDense[bA[c]]);
#pragma unroll
            for (int c = 0; c < 4; c++) {
                u64 t = mul2(pk2(v[c].x, v[c].y), wx02);
                t = fma2(pk2(v[c].z, v[c].w), fx2, t);
                acc = fma2(t, pk2(wyzA[c], wyzA[c]), acc);
            }
        } else {
            const float2* __restrict__ tl = tab + (size_t)l * TSIZE;
            const float4* __restrict__ tl4 = (const float4*)tl;
            unsigned ty0 = cy * P2, ty1 = ty0 + P2;
            unsigned tz0 = cz * P3, tz1 = tz0 + P3;
            unsigned mask = cx ^ (cx + 1u);
            unsigned np = cx & 1u;

            float4 v[4];
            float2 t2[4];
            unsigned jloA[4];
#pragma unroll
            for (int c = 0; c < 4; c++) {
                unsigned H = ((c & 1u) ? ty1 : ty0) ^ ((c & 2u) ? tz1 : tz0);
                unsigned jlo = (cx ^ H) & TMASK;
                unsigned jhi = (jlo ^ mask) & TMASK;
                jloA[c] = jlo;
                v[c] = __ldg(tl4 + (jlo >> 1));
                t2[c] = cond_ldg_f2_indep(tl + jhi, np);
            }
#pragma unroll
            for (int c = 0; c < 4; c++) {
                unsigned odd = jloA[c] & 1u;
                float2 flo = odd ? make_float2(v[c].z, v[c].w) : make_float2(v[c].x, v[c].y);
                float2 oth = odd ? make_float2(v[c].x, v[c].y) : make_float2(v[c].z, v[c].w);
                float2 fhi = np ? t2[c] : oth;
                u64 t = mul2(pk2(flo.x, flo.y), wx02);
                t = fma2(pk2(fhi.x, fhi.y), fx2, t);
                acc = fma2(t, pk2(wyzA[c], wyzA[c]), acc);
            }
        }
        enc2[l] = acc;
    }

    const u64* __restrict__ w0q = (const u64*)cAll;
    const u64* __restrict__ w1q = (const u64*)(cAll + OW1);
    const float* __restrict__ cb0 = cAll + OB0;
    const float* __restrict__ cb1 = cAll + OB1;

    u64 acc2[OUTDIM / 2];
#pragma unroll
    for (int o2 = 0; o2 < OUTDIM / 2; o2++)
        acc2[o2] = pk2(cb1[2 * o2], cb1[2 * o2 + 1]);

#pragma unroll 8
    for (int j = 0; j < HIDDEN; j++) {
        u64 h2 = pk2(cb0[j], 0.0f);
#pragma unroll
        for (int k2 = 0; k2 < NLEVELS; k2++)
            h2 = fma2(enc2[k2], w0q[j * NLEVELS + k2], h2);
        float hlo, hhi;
        upk2(hlo, hhi, h2);
        float h = hlo + hhi;

        float z = 100.0f * h;
        float sp = __logf(1.0f + __expf(z)) * 0.01f;
        float a = (z > 20.0f) ? h : sp;

        u64 a2 = pk2(a, a);
#pragma unroll
        for (int o2 = 0; o2 < OUTDIM / 2; o2++)
            acc2[o2] = fma2(a2, w1q[j * (OUTDIM / 2) + o2], acc2[o2]);
    }

    float acc[OUTDIM];
#pragma unroll
    for (int o2 = 0; o2 < OUTDIM / 2; o2++)
        upk2(acc[2 * o2], acc[2 * o2 + 1], acc2[o2]);

    // phase 2: reuse sBuf as sGeo staging (table no longer needed)
    __syncthreads();
    float* __restrict__ sGeo = sBuf;
#pragma unroll
    for (int o = 0; o < 15; o++) sGeo[tid * 15 + o] = acc[o + 1];
    if (valid) out[i] = acc[0];
    __syncthreads();

    float* __restrict__ geo = out + N;
    size_t gbase = (size_t)iBase * 15;
    int remain = N - iBase;
    if (remain >= TPB) {
        const float4* __restrict__ s4 = (const float4*)sGeo;
        float4* __restrict__ g4 = (float4*)(geo + gbase);
        for (int t = tid; t < TPB * 15 / 4; t += TPB)
            g4[t] = s4[t];
    } else {
        int total = remain * 15;
        for (int t = tid; t < total; t += TPB)
            geo[gbase + t] = sGeo[t];
    }
}

extern "C" void kernel_launch(void* const* d_in, const int* in_sizes, int n_in,
                              void* d_out, int out_size)
{
    const float* x     = (const float*)d_in[0];
    const float* table = (const float*)d_in[1];
    const float* W0    = (const float*)d_in[2];
    const float* b0    = (const float*)d_in[3];
    const float* W1    = (const float*)d_in[4];
    const float* b1    = (const float*)d_in[5];
    float* out = (float*)d_out;

    int N = in_sizes[0] / 3;

    setup_kernel<<<(DTOT + 255) / 256, 256>>>(table, W0, b0, W1, b1);
    void* stage = nullptr;
    cudaGetSymbolAddress(&stage, gStage);
    cudaMemcpyToSymbolAsync(cAll, stage, CTOT * sizeof(float), 0,
                            cudaMemcpyDeviceToDevice, 0);

    Params p;
    const double pls = exp2(7.0 / 15.0);
    for (int l = 0; l < NLEVELS; l++) {
        double sc = 16.0 * pow(pls, (double)l) - 1.0;
        p.scale[l] = (float)sc;
    }

    int blocks = (N + TPB - 1) / TPB;
    sdf_fused_kernel<<<blocks, TPB>>>(x, table, out, N, p);
}